// round 17
// baseline (speedup 1.0000x reference)
#include <cuda_runtime.h>

#define B_N   1024
#define C_N   128
#define I_N   16
#define E_N   10
#define NT3   816           // cubic monomials i0<=i1<=i2
#define NT2   136           // quadratic monomials
#define NT    968           // slab entries per (species, comp-half)
#define QOFF  NT3
#define LOFF  (NT3 + NT2)
#define NCOMP 4
#define NQMAX 288           // >= max quads (<= 266)
#define NTHR  544           // 17 warps; >= 2*NQMAX tasks never exceeds 532

// ---------------- device scratch (static globals; no allocation) ----------------
__device__ int4  g_quad[NQMAX];   // 4 item ids (same species, padded by repeat)
__device__ int   g_qe[NQMAX];     // species of quad
__device__ int   g_nq;
__device__ __align__(32) float g_U3S[NCOMP][NT3][8];
__device__ __align__(16) float g_U2S[NCOMP][NT2][4];
__device__ float g_U1S[NCOMP][I_N];

// ---------------- kernel A: quad build (block 0) + U sym (blocks 1..32) ---------
__global__ void prep_kernel(const float* __restrict__ node_attrs,
                            const float* __restrict__ U3_l0,
                            const float* __restrict__ U3_l1,
                            const float* __restrict__ U2_l0,
                            const float* __restrict__ U2_l1,
                            const float* __restrict__ U1_l0,
                            const float* __restrict__ U1_l1) {
    int tid = threadIdx.x;   // 1024
    if (blockIdx.x == 0) {
        __shared__ int s_hist[E_N], s_off[E_N], s_start[E_N], s_end[E_N], s_qbase[E_N];
        __shared__ int s_perm[B_N];
        if (tid < E_N) s_hist[tid] = 0;
        __syncthreads();
        const float* na = node_attrs + tid * E_N;
        int e = 0;
#pragma unroll
        for (int j = 0; j < E_N; j++) if (na[j] > 0.5f) e = j;
        atomicAdd(&s_hist[e], 1);
        __syncthreads();
        if (tid == 0) {
            int acc = 0, qacc = 0;
            for (int j = 0; j < E_N; j++) {
                s_start[j] = acc; s_off[j] = acc; s_qbase[j] = qacc;
                qacc += (s_hist[j] + 3) >> 2;
                acc  += s_hist[j];
                s_end[j] = acc;
            }
            g_nq = qacc;
        }
        __syncthreads();
        int pos = atomicAdd(&s_off[e], 1);
        s_perm[pos] = tid;
        __syncthreads();
        int off = pos - s_start[e];
        if ((off & 3) == 0) {
            int q    = s_qbase[e] + (off >> 2);
            int last = s_end[e] - 1;
            int p1 = (pos + 1 <= last) ? pos + 1 : last;
            int p2 = (pos + 2 <= last) ? pos + 2 : last;
            int p3 = (pos + 3 <= last) ? pos + 3 : last;
            g_quad[q] = make_int4(tid, s_perm[p1], s_perm[p2], s_perm[p3]);
            g_qe[q]   = e;
        }
        return;
    }

    int gtid = (blockIdx.x - 1) * blockDim.x + tid;   // 0..32767

    if (gtid < NCOMP * NT3 * 8) {
        int k    = gtid & 7;
        int t    = (gtid >> 3) % NT3;
        int comp = gtid / (NT3 * 8);
        int rem = t, a = 0;
        for (int ap = 0; ap < I_N; ap++) {
            int sz = (I_N - ap) * (I_N - ap + 1) / 2;
            if (rem < sz) { a = ap; break; }
            rem -= sz;
        }
        int b = a;
        for (int bp = a; bp < I_N; bp++) {
            int sz = I_N - bp;
            if (rem < sz) { b = bp; break; }
            rem -= sz;
        }
        int c = b + rem;
        float inv = (a == c) ? (1.f / 6.f) : ((a == b || b == c) ? 0.5f : 1.f);
        int kN; const float* U;
        if (comp == 0) { kN = 5; U = U3_l0; }
        else           { kN = 7; U = U3_l1 + (comp - 1) * (I_N * I_N * I_N * 7); }
        float s = 0.f;
        if (k < kN) {
            auto at = [&](int i0, int i1, int i2) {
                return U[((i0 * I_N + i1) * I_N + i2) * kN + k];
            };
            s = at(a,b,c) + at(a,c,b) + at(b,a,c) + at(b,c,a) + at(c,a,b) + at(c,b,a);
            s *= inv;
        }
        g_U3S[comp][t][k] = s;
    }
    if (gtid < NCOMP * NT2 * 4) {
        int k    = gtid & 3;
        int t    = (gtid >> 2) % NT2;
        int comp = gtid / (NT2 * 4);
        int rem = t, a = 0;
        for (int ap = 0; ap < I_N; ap++) {
            int sz = I_N - ap;
            if (rem < sz) { a = ap; break; }
            rem -= sz;
        }
        int b = a + rem;
        int kN; const float* U;
        if (comp == 0) { kN = 2; U = U2_l0; }
        else           { kN = 3; U = U2_l1 + (comp - 1) * (I_N * I_N * 3); }
        float s = 0.f;
        if (k < kN) {
            s = U[(a * I_N + b) * kN + k];
            if (a != b) s += U[(b * I_N + a) * kN + k];
        }
        g_U2S[comp][t][k] = s;
    }
    if (gtid < NCOMP * I_N) {
        int comp = gtid / I_N, i = gtid % I_N;
        g_U1S[comp][i] = (comp == 0) ? U1_l0[i] : U1_l1[(comp - 1) * I_N + i];
    }
}

// ---------------- kernel B: fused fold + evaluation, block = channel ------------
// 544 threads. Task = (quad of 4 same-species items, comp-half): one float2
// coefficient LDS feeds 8 FFMA across 4 items -> LDS wavefronts per SM halved
// vs R14 (R16 evidence: kernel is LDS data-volume bound).
__global__ void __launch_bounds__(NTHR, 1) main_kernel(const float* __restrict__ a_i,
                                                       const float* __restrict__ W3_l0,
                                                       const float* __restrict__ W2_l0,
                                                       const float* __restrict__ W1_l0,
                                                       const float* __restrict__ W3_l1,
                                                       const float* __restrict__ W2_l1,
                                                       const float* __restrict__ W1_l1,
                                                       float* __restrict__ out) {
    extern __shared__ __align__(16) float2 s_raw[];   // [2 * E_N * NT] = 154.9 KB
    float2* s01 = s_raw;
    float2* s23 = s_raw + E_N * NT;
    __shared__ float sw30[E_N][5], sw31[E_N][7];
    __shared__ float sw20[E_N][2], sw21[E_N][3];
    __shared__ float sw10[E_N], sw11[E_N];
    int c   = blockIdx.x;
    int tid = threadIdx.x;

    // ---- stage per-channel species weights ----------------------------------
    if (tid < E_N * 5) sw30[tid / 5][tid % 5] = W3_l0[tid * C_N + c];
    if (tid < E_N * 7) sw31[tid / 7][tid % 7] = W3_l1[tid * C_N + c];
    if (tid < E_N * 2) sw20[tid / 2][tid % 2] = W2_l0[tid * C_N + c];
    if (tid < E_N * 3) sw21[tid / 3][tid % 3] = W2_l1[tid * C_N + c];
    if (tid < E_N) { sw10[tid] = W1_l0[tid * C_N + c]; sw11[tid] = W1_l1[tid * C_N + c]; }
    __syncthreads();

    // ---- fold: coefficients for all species, straight into SMEM -------------
    for (int t = tid; t < NT3; t += NTHR) {
        float4 A0 = reinterpret_cast<const float4*>(&g_U3S[0][t][0])[0];
        float4 A1 = reinterpret_cast<const float4*>(&g_U3S[0][t][0])[1];
        float4 B0 = reinterpret_cast<const float4*>(&g_U3S[1][t][0])[0];
        float4 B1 = reinterpret_cast<const float4*>(&g_U3S[1][t][0])[1];
        float4 C0 = reinterpret_cast<const float4*>(&g_U3S[2][t][0])[0];
        float4 C1 = reinterpret_cast<const float4*>(&g_U3S[2][t][0])[1];
        float4 D0 = reinterpret_cast<const float4*>(&g_U3S[3][t][0])[0];
        float4 D1 = reinterpret_cast<const float4*>(&g_U3S[3][t][0])[1];
#pragma unroll
        for (int e = 0; e < E_N; e++) {
            float c0 = A0.x*sw30[e][0] + A0.y*sw30[e][1] + A0.z*sw30[e][2]
                     + A0.w*sw30[e][3] + A1.x*sw30[e][4];
            float c1 = B0.x*sw31[e][0] + B0.y*sw31[e][1] + B0.z*sw31[e][2]
                     + B0.w*sw31[e][3] + B1.x*sw31[e][4] + B1.y*sw31[e][5] + B1.z*sw31[e][6];
            float c2 = C0.x*sw31[e][0] + C0.y*sw31[e][1] + C0.z*sw31[e][2]
                     + C0.w*sw31[e][3] + C1.x*sw31[e][4] + C1.y*sw31[e][5] + C1.z*sw31[e][6];
            float c3 = D0.x*sw31[e][0] + D0.y*sw31[e][1] + D0.z*sw31[e][2]
                     + D0.w*sw31[e][3] + D1.x*sw31[e][4] + D1.y*sw31[e][5] + D1.z*sw31[e][6];
            s01[e * NT + t] = make_float2(c0, c1);
            s23[e * NT + t] = make_float2(c2, c3);
        }
    }
    for (int t = tid; t < NT2; t += NTHR) {
        float4 Q0 = reinterpret_cast<const float4*>(&g_U2S[0][t][0])[0];
        float4 Q1 = reinterpret_cast<const float4*>(&g_U2S[1][t][0])[0];
        float4 Q2 = reinterpret_cast<const float4*>(&g_U2S[2][t][0])[0];
        float4 Q3 = reinterpret_cast<const float4*>(&g_U2S[3][t][0])[0];
#pragma unroll
        for (int e = 0; e < E_N; e++) {
            float c0 = Q0.x*sw20[e][0] + Q0.y*sw20[e][1];
            float c1 = Q1.x*sw21[e][0] + Q1.y*sw21[e][1] + Q1.z*sw21[e][2];
            float c2 = Q2.x*sw21[e][0] + Q2.y*sw21[e][1] + Q2.z*sw21[e][2];
            float c3 = Q3.x*sw21[e][0] + Q3.y*sw21[e][1] + Q3.z*sw21[e][2];
            s01[e * NT + QOFF + t] = make_float2(c0, c1);
            s23[e * NT + QOFF + t] = make_float2(c2, c3);
        }
    }
    if (tid < I_N) {
        int i = tid;
#pragma unroll
        for (int e = 0; e < E_N; e++) {
            s01[e * NT + LOFF + i] =
                make_float2(g_U1S[0][i] * sw10[e], g_U1S[1][i] * sw11[e]);
            s23[e * NT + LOFF + i] =
                make_float2(g_U1S[2][i] * sw11[e], g_U1S[3][i] * sw11[e]);
        }
    }
    __syncthreads();

    // ---- eval: one (quad, comp-half) task per thread -------------------------
    int nq = g_nq;
    if (tid >= 2 * nq) return;
    int h = (tid >= nq) ? 1 : 0;
    int q = tid - h * nq;
    int4 qd = g_quad[q];
    const float2* base = (h ? s23 : s01) + g_qe[q] * NT;

    float x0[16], x1[16], x2[16], x3[16];
#define LOADX(arr, item)                                                          \
    {                                                                             \
        const float4* xp = reinterpret_cast<const float4*>(                       \
            a_i + ((item) * C_N + c) * I_N);                                      \
        float4 v0 = xp[0], v1 = xp[1], v2 = xp[2], v3 = xp[3];                    \
        arr[0]=v0.x;  arr[1]=v0.y;  arr[2]=v0.z;  arr[3]=v0.w;                    \
        arr[4]=v1.x;  arr[5]=v1.y;  arr[6]=v1.z;  arr[7]=v1.w;                    \
        arr[8]=v2.x;  arr[9]=v2.y;  arr[10]=v2.z; arr[11]=v2.w;                   \
        arr[12]=v3.x; arr[13]=v3.y; arr[14]=v3.z; arr[15]=v3.w;                   \
    }
    LOADX(x0, qd.x) LOADX(x1, qd.y) LOADX(x2, qd.z) LOADX(x3, qd.w)
#undef LOADX

    float ou0 = 0.f, ou1 = 0.f, ou2 = 0.f, ou3 = 0.f;
    float ov0 = 0.f, ov1 = 0.f, ov2 = 0.f, ov3 = 0.f;
    int t = 0, tp = 0;
#pragma unroll
    for (int a = 0; a < I_N; a++) {
        float t2u0, t2u1, t2u2, t2u3, t2v0, t2v1, t2v2, t2v3;
        float2 cl = base[LOFF + a];
#pragma unroll
        for (int b2 = a; b2 < I_N; b2++) {
            float2 cq = base[QOFF + tp]; tp++;
            float t3u0, t3u1, t3u2, t3u3, t3v0, t3v1, t3v2, t3v3;
            {
                float2 cf = base[t]; t++;   // c3 == b2 absorbs quad coef
                t3u0 = fmaf(cf.x, x0[b2], cq.x);  t3u1 = fmaf(cf.x, x1[b2], cq.x);
                t3u2 = fmaf(cf.x, x2[b2], cq.x);  t3u3 = fmaf(cf.x, x3[b2], cq.x);
                t3v0 = fmaf(cf.y, x0[b2], cq.y);  t3v1 = fmaf(cf.y, x1[b2], cq.y);
                t3v2 = fmaf(cf.y, x2[b2], cq.y);  t3v3 = fmaf(cf.y, x3[b2], cq.y);
            }
#pragma unroll
            for (int c3 = b2 + 1; c3 < I_N; c3++) {
                float2 cf = base[t]; t++;
                t3u0 = fmaf(cf.x, x0[c3], t3u0);  t3u1 = fmaf(cf.x, x1[c3], t3u1);
                t3u2 = fmaf(cf.x, x2[c3], t3u2);  t3u3 = fmaf(cf.x, x3[c3], t3u3);
                t3v0 = fmaf(cf.y, x0[c3], t3v0);  t3v1 = fmaf(cf.y, x1[c3], t3v1);
                t3v2 = fmaf(cf.y, x2[c3], t3v2);  t3v3 = fmaf(cf.y, x3[c3], t3v3);
            }
            if (b2 == a) {   // first b-fold absorbs linear coef
                t2u0 = fmaf(t3u0, x0[b2], cl.x);  t2u1 = fmaf(t3u1, x1[b2], cl.x);
                t2u2 = fmaf(t3u2, x2[b2], cl.x);  t2u3 = fmaf(t3u3, x3[b2], cl.x);
                t2v0 = fmaf(t3v0, x0[b2], cl.y);  t2v1 = fmaf(t3v1, x1[b2], cl.y);
                t2v2 = fmaf(t3v2, x2[b2], cl.y);  t2v3 = fmaf(t3v3, x3[b2], cl.y);
            } else {
                t2u0 = fmaf(t3u0, x0[b2], t2u0);  t2u1 = fmaf(t3u1, x1[b2], t2u1);
                t2u2 = fmaf(t3u2, x2[b2], t2u2);  t2u3 = fmaf(t3u3, x3[b2], t2u3);
                t2v0 = fmaf(t3v0, x0[b2], t2v0);  t2v1 = fmaf(t3v1, x1[b2], t2v1);
                t2v2 = fmaf(t3v2, x2[b2], t2v2);  t2v3 = fmaf(t3v3, x3[b2], t2v3);
            }
        }
        ou0 = fmaf(t2u0, x0[a], ou0);  ou1 = fmaf(t2u1, x1[a], ou1);
        ou2 = fmaf(t2u2, x2[a], ou2);  ou3 = fmaf(t2u3, x3[a], ou3);
        ov0 = fmaf(t2v0, x0[a], ov0);  ov1 = fmaf(t2v1, x1[a], ov1);
        ov2 = fmaf(t2v2, x2[a], ov2);  ov3 = fmaf(t2v3, x3[a], ov3);
    }

    // output: [b, 512] = concat(out0[b,c], out1[b, c*3+m])
    // h=0 -> comps 0 (ob[c]) and 1; h=1 -> comps 2 and 3.
    // Padded duplicate items: same thread rewrites same addr with same value.
    int addrU = h ? (128 + c * 3 + 1) : c;
    int addrV = h ? (128 + c * 3 + 2) : (128 + c * 3);
    out[qd.x * 512 + addrU] = ou0;  out[qd.x * 512 + addrV] = ov0;
    out[qd.y * 512 + addrU] = ou1;  out[qd.y * 512 + addrV] = ov1;
    out[qd.z * 512 + addrU] = ou2;  out[qd.z * 512 + addrV] = ov2;
    out[qd.w * 512 + addrU] = ou3;  out[qd.w * 512 + addrV] = ov3;
}

// ---------------- launch --------------------------------------------------------
extern "C" void kernel_launch(void* const* d_in, const int* in_sizes, int n_in,
                              void* d_out, int out_size) {
    const float* a_i   = (const float*)d_in[0];
    const float* na    = (const float*)d_in[1];
    const float* U3_l0 = (const float*)d_in[2];
    const float* U2_l0 = (const float*)d_in[3];
    const float* U1_l0 = (const float*)d_in[4];
    const float* W3_l0 = (const float*)d_in[5];
    const float* W2_l0 = (const float*)d_in[6];
    const float* W1_l0 = (const float*)d_in[7];
    const float* U3_l1 = (const float*)d_in[8];
    const float* U2_l1 = (const float*)d_in[9];
    const float* U1_l1 = (const float*)d_in[10];
    const float* W3_l1 = (const float*)d_in[11];
    const float* W2_l1 = (const float*)d_in[12];
    const float* W1_l1 = (const float*)d_in[13];
    float* out = (float*)d_out;

    const int smem_bytes = 2 * E_N * NT * (int)sizeof(float2);  // 154880
    cudaFuncSetAttribute(main_kernel, cudaFuncAttributeMaxDynamicSharedMemorySize,
                         smem_bytes);

    prep_kernel<<<33, 1024>>>(na, U3_l0, U3_l1, U2_l0, U2_l1, U1_l0, U1_l1);
    main_kernel<<<C_N, NTHR, smem_bytes>>>(a_i, W3_l0, W2_l0, W1_l0,
                                           W3_l1, W2_l1, W1_l1, out);
}